// round 16
// baseline (speedup 1.0000x reference)
#include <cuda_runtime.h>

#define N_BINS 10
#define GRID_BLOCKS 592     // 148 SMs * 4 blocks -> one wave at occ 4
#define BLOCK_THREADS 256
#define TOTAL_WARPS (GRID_BLOCKS * (BLOCK_THREADS / 32))

// Global scratch (no allocations allowed). Zero-initialized at module load;
// the last finishing block resets them, so "zeroed at entry" holds across
// graph replays.
__device__ double g_cnt[N_BINS];
__device__ double g_conf[N_BINS];
__device__ double g_acc[N_BINS];
__device__ unsigned g_done;

__device__ __forceinline__ float ex2(float x) {
    float r;
    asm("ex2.approx.f32 %0, %1;" : "=f"(r) : "f"(x));
    return r;
}

// Two rows per warp: lanes 0-15 handle one row, lanes 16-31 the next.
// Cross-lane reduction: full-constant-mask shfl_xor at offsets 8,4,2,1 --
// never crosses the 16-lane boundary, so each half reduces independently
// while every SHFL is a single hardware instruction.
// Each lane holds 8 columns of its row: cols 4*hl..4*hl+3 (A) and
// 64+4*hl..64+4*hl+3 (B). lab = label of THIS lane's row.
// Lane hl of each half accumulates bin hl.
__device__ __forceinline__ void ece_pair(
    float4 A, float4 B, int lab, int hl,
    bool acc_en,
    float& r_cnt, float& r_conf, float& r_acc)
{
    const float L2E = 1.4426950408889634f;
    float e0 = ex2(A.x * L2E);
    float e1 = ex2(A.y * L2E);
    float e2 = ex2(A.z * L2E);
    float e3 = ex2(A.w * L2E);
    float e4 = ex2(B.x * L2E);
    float e5 = ex2(B.y * L2E);
    float e6 = ex2(B.z * L2E);
    float e7 = ex2(B.w * L2E);

    // Local sum + local max of the 8 exps.
    float s = ((e0 + e1) + (e2 + e3)) + ((e4 + e5) + (e6 + e7));
    float m = fmaxf(fmaxf(fmaxf(e0, e1), fmaxf(e2, e3)),
                    fmaxf(fmaxf(e4, e5), fmaxf(e6, e7)));

    // Does MY lane own the label column, and does it attain my local max?
    int sub = lab & 3;
    float elo = (sub & 2) ? ((sub & 1) ? e3 : e2) : ((sub & 1) ? e1 : e0);
    float ehi = (sub & 2) ? ((sub & 1) ? e7 : e6) : ((sub & 1) ? e5 : e4);
    float vl  = (lab & 64) ? ehi : elo;
    unsigned bit = (((lab >> 2) & 15) == hl) && (vl == m);

    // Packed key: exps are positive (bits < 2^31), so (bits<<1)|correct is
    // order-preserving in m.
    unsigned k = (__float_as_uint(m) << 1) | bit;

    // Segmented butterfly reduction within each 16-lane half.
    #pragma unroll
    for (int o = 8; o; o >>= 1) {
        s += __shfl_xor_sync(0xffffffffu, s, o);
        unsigned ok = __shfl_xor_sync(0xffffffffu, k, o);
        k = max(k, ok);
    }
    float wm = __uint_as_float(k >> 1);

    float conf = __fdividef(wm, s);                       // max softmax prob
    int b1 = min((int)ceilf(conf * 10.0f), N_BINS);       // in [1,10]
    if (acc_en && b1 == hl + 1) {
        r_cnt  += 1.0f;
        r_conf += conf;
        r_acc  += (float)(k & 1u);
    }
}

__global__ void __launch_bounds__(BLOCK_THREADS, 4) ece_fused(
    const float* __restrict__ logits,
    const int* __restrict__ labels,
    int n_rows,
    float* __restrict__ out)
{
    __shared__ float s_c[N_BINS], s_f[N_BINS], s_a[N_BINS];

    int tid = threadIdx.x;
    if (tid < N_BINS) { s_c[tid] = 0.0f; s_f[tid] = 0.0f; s_a[tid] = 0.0f; }

    const int lane  = tid & 31;
    const int half  = lane >> 4;           // 0: even row of pair, 1: odd row
    const int hl    = lane & 15;
    const int warp  = tid >> 5;
    const int gwarp = blockIdx.x * (BLOCK_THREADS / 32) + warp;

    const float4* __restrict__ lrows = (const float4*)logits;

    float r_cnt = 0.0f, r_conf = 0.0f, r_acc = 0.0f;

    // 4 pairs (8 rows = 4KB) per iteration: 8 LDG.128 hoisted for maximum
    // per-warp MLP; loop overhead amortized over four pairs.
    const int n_pairs = n_rows >> 1;
    const int n_octs  = n_pairs >> 2;      // iterations of the 4-pair loop
    const float4* __restrict__ p = lrows + (size_t)gwarp * 256 + (half << 5) + hl;
    const int4*   __restrict__ lp = (const int4*)labels + gwarp * 2;

    #pragma unroll 1
    for (int q = gwarp; q < n_octs; q += TOTAL_WARPS) {
        float4 A0 = p[0],   B0 = p[16];
        float4 A1 = p[64],  B1 = p[80];
        float4 A2 = p[128], B2 = p[144];
        float4 A3 = p[192], B3 = p[208];
        int4   L0 = lp[0];
        int4   L1 = lp[1];

        ece_pair(A0, B0, half ? L0.y : L0.x, hl, true, r_cnt, r_conf, r_acc);
        ece_pair(A1, B1, half ? L0.w : L0.z, hl, true, r_cnt, r_conf, r_acc);
        ece_pair(A2, B2, half ? L1.y : L1.x, hl, true, r_cnt, r_conf, r_acc);
        ece_pair(A3, B3, half ? L1.w : L1.z, hl, true, r_cnt, r_conf, r_acc);

        p  += (size_t)TOTAL_WARPS * 256;
        lp += TOTAL_WARPS * 2;
    }

    // Tail pairs (n_pairs % 4) handled per-pair by warp 0.
    if (gwarp == 0) {
        for (int pr = n_octs * 4; pr < n_pairs; pr++) {
            const float4* q4 = lrows + (size_t)pr * 64 + (half << 5) + hl;
            float4 A = q4[0], B = q4[16];
            int lab = labels[pr * 2 + half];
            ece_pair(A, B, lab, hl, true, r_cnt, r_conf, r_acc);
        }
        // Odd leftover row (n_rows odd): halves mirror the row, half 0 counts.
        if (n_rows & 1) {
            int r = n_rows - 1;
            const float4* q4 = lrows + (size_t)r * 32 + hl;
            float4 A = q4[0], B = q4[16];
            ece_pair(A, B, labels[r], hl, half == 0, r_cnt, r_conf, r_acc);
        }
    }

    // Block reduction: lane hl (<10) of each half holds bin hl partials.
    __syncthreads();                   // also covers the s_* zero-init
    if (hl < N_BINS) {
        atomicAdd(&s_c[hl], r_cnt);
        atomicAdd(&s_f[hl], r_conf);
        atomicAdd(&s_a[hl], r_acc);
    }
    __syncthreads();

    if (tid < N_BINS) {
        atomicAdd(&g_cnt[tid],  (double)s_c[tid]);
        atomicAdd(&g_conf[tid], (double)s_f[tid]);
        atomicAdd(&g_acc[tid],  (double)s_a[tid]);
        __threadfence();               // order bin atomics before done-ticket
    }
    __syncthreads();

    // Last block finalizes and resets scratch for the next graph replay.
    if (tid == 0) {
        unsigned ticket = atomicAdd(&g_done, 1u);
        if (ticket == GRID_BLOCKS - 1) {
            double ece = 0.0, oe = 0.0;
            #pragma unroll
            for (int i = 0; i < N_BINS; i++) {
                double cnt = atomicAdd(&g_cnt[i],  0.0);
                double cf  = atomicAdd(&g_conf[i], 0.0);
                double ac  = atomicAdd(&g_acc[i],  0.0);
                bool nonempty = cnt > 0.0;
                double prop  = cnt / (double)n_rows;
                double denom = nonempty ? cnt : 1.0;
                double accb  = nonempty ? ac / denom : 0.0;
                double cfb   = nonempty ? cf / denom : 0.0;
                double CE    = cfb - accb;
                double absCE = nonempty ? fabs(CE) : 0.0;
                ece += absCE * prop;
                oe  += (nonempty ? cfb * fmax(CE, 0.0) : 0.0) * prop;
                out[1 + i]  = (float)accb;
                out[12 + i] = (float)prop;
                out[22 + i] = (float)absCE;
                g_cnt[i] = 0.0; g_conf[i] = 0.0; g_acc[i] = 0.0;
            }
            out[0]  = (float)ece;
            out[11] = (float)oe;
            g_done = 0u;
            __threadfence();
        }
    }
}

extern "C" void kernel_launch(void* const* d_in, const int* in_sizes, int n_in,
                              void* d_out, int out_size) {
    const float* logits = (const float*)d_in[0];
    const int*   labels = (const int*)d_in[1];
    float*       out    = (float*)d_out;

    int n_rows = in_sizes[0] / 128;   // C = 128

    ece_fused<<<GRID_BLOCKS, BLOCK_THREADS>>>(logits, labels, n_rows, out);
}